// round 2
// baseline (speedup 1.0000x reference)
#include <cuda_runtime.h>
#include <math.h>

#define B 512
#define D 256
#define HH 32
#define WW 32
#define TINV 10.0f  // 1/TEMPERATURE

// ---------------- scratch (no allocations allowed) ----------------
__device__ float g_d1[B * D];
__device__ float g_d2[B * D];
__device__ float g_n1[B];
__device__ float g_n2[B];
__device__ float g_sim[B * B];
__device__ float g_rowmax[B];
__device__ float g_colmax[B];
__device__ float g_rowden[B];
__device__ float g_colden[B];

// ---------------- kernel 1: masked avg-pool descriptors + norms ----------------
// grid (B, 2), block 256. Lane = x pixel (W==32), warp handles 32 channels,
// 8 channels in flight per inner loop for MLP.
__global__ void desc_kernel(const float* __restrict__ f1,
                            const float* __restrict__ f2,
                            const float* __restrict__ bb1,
                            const float* __restrict__ bb2) {
    const int b = blockIdx.x;
    const int which = blockIdx.y;
    const float* __restrict__ src = which ? f2 : f1;
    const float* __restrict__ box = which ? bb2 : bb1;
    float* __restrict__ gd = which ? g_d2 : g_d1;
    float* __restrict__ gn = which ? g_n2 : g_n1;

    const int tid = threadIdx.x;
    const int lane = tid & 31;
    const int warp = tid >> 5;

    const float x0 = box[b * 4 + 0];
    const float y0 = box[b * 4 + 1];
    const float x1 = box[b * 4 + 2];
    const float y1 = box[b * 4 + 3];

    // x mask for this lane (exact same fp ops as reference: (i+0.5)/32)
    const float xc = ((float)lane + 0.5f) / 32.0f;
    const bool inx = (xc >= x0) && (xc <= x1);

    // y range (contiguous)
    int iy0 = 32, iy1 = -1;
#pragma unroll
    for (int y = 0; y < 32; y++) {
        float yc = ((float)y + 0.5f) / 32.0f;
        if (yc >= y0 && yc <= y1) { if (y < iy0) iy0 = y; iy1 = y; }
    }
    const int nx = __popc(__ballot_sync(0xffffffffu, inx));
    const int ny = (iy1 >= iy0) ? (iy1 - iy0 + 1) : 0;
    int cnt = nx * ny; if (cnt < 1) cnt = 1;
    const float inv_denom = 1.0f / (float)cnt;

    __shared__ float sdesc[D];
    __shared__ float sred[256];

    const float* base = src + (size_t)b * D * (HH * WW);

    // warp `warp` handles channels [warp*32, warp*32+32), 8 at a time
    for (int dd = 0; dd < 32; dd += 8) {
        const int d0 = (warp << 5) + dd;
        const float* p = base + (size_t)d0 * (HH * WW) + lane;
        float s0 = 0.f, s1 = 0.f, s2 = 0.f, s3 = 0.f;
        float s4 = 0.f, s5 = 0.f, s6 = 0.f, s7 = 0.f;
        for (int y = iy0; y <= iy1; y++) {
            const float* q = p + y * WW;
            if (inx) {
                s0 += q[0 * 1024]; s1 += q[1 * 1024];
                s2 += q[2 * 1024]; s3 += q[3 * 1024];
                s4 += q[4 * 1024]; s5 += q[5 * 1024];
                s6 += q[6 * 1024]; s7 += q[7 * 1024];
            }
        }
#pragma unroll
        for (int o = 16; o; o >>= 1) {
            s0 += __shfl_xor_sync(0xffffffffu, s0, o);
            s1 += __shfl_xor_sync(0xffffffffu, s1, o);
            s2 += __shfl_xor_sync(0xffffffffu, s2, o);
            s3 += __shfl_xor_sync(0xffffffffu, s3, o);
            s4 += __shfl_xor_sync(0xffffffffu, s4, o);
            s5 += __shfl_xor_sync(0xffffffffu, s5, o);
            s6 += __shfl_xor_sync(0xffffffffu, s6, o);
            s7 += __shfl_xor_sync(0xffffffffu, s7, o);
        }
        if (lane == 0) {
            sdesc[d0 + 0] = s0 * inv_denom;
            sdesc[d0 + 1] = s1 * inv_denom;
            sdesc[d0 + 2] = s2 * inv_denom;
            sdesc[d0 + 3] = s3 * inv_denom;
            sdesc[d0 + 4] = s4 * inv_denom;
            sdesc[d0 + 5] = s5 * inv_denom;
            sdesc[d0 + 6] = s6 * inv_denom;
            sdesc[d0 + 7] = s7 * inv_denom;
        }
    }
    __syncthreads();

    const float v = sdesc[tid];
    gd[b * D + tid] = v;

    sred[tid] = v * v;
    __syncthreads();
    for (int s = 128; s; s >>= 1) {
        if (tid < s) sred[tid] += sred[tid + s];
        __syncthreads();
    }
    if (tid == 0) gn[b] = sqrtf(sred[0]);
}

// ---------------- kernel 2: sim = (d1 @ d2^T) / max(n1*n2, eps) ----------------
// 64x64 tile per block, 16x16 threads, 4x4 microtile, K chunked by 64.
__global__ void sim_kernel() {
    __shared__ float As[64][68];
    __shared__ float Bs[64][68];

    const int tx = threadIdx.x & 15;
    const int ty = threadIdx.x >> 4;
    const int i0 = blockIdx.y * 64;
    const int j0 = blockIdx.x * 64;

    float acc[4][4];
#pragma unroll
    for (int r = 0; r < 4; r++)
#pragma unroll
        for (int c = 0; c < 4; c++) acc[r][c] = 0.f;

    for (int kt = 0; kt < D; kt += 64) {
        for (int l = threadIdx.x; l < 64 * 64; l += 256) {
            const int kk = l & 63;
            const int row = l >> 6;
            As[kk][row] = g_d1[(i0 + row) * D + kt + kk];
            Bs[kk][row] = g_d2[(j0 + row) * D + kt + kk];
        }
        __syncthreads();
#pragma unroll 8
        for (int kk = 0; kk < 64; kk++) {
            float4 a = *(const float4*)&As[kk][ty * 4];
            float4 bv = *(const float4*)&Bs[kk][tx * 4];
            float av[4] = {a.x, a.y, a.z, a.w};
            float bw[4] = {bv.x, bv.y, bv.z, bv.w};
#pragma unroll
            for (int r = 0; r < 4; r++)
#pragma unroll
                for (int c = 0; c < 4; c++) acc[r][c] += av[r] * bw[c];
        }
        __syncthreads();
    }

#pragma unroll
    for (int r = 0; r < 4; r++) {
        const int i = i0 + ty * 4 + r;
        const float ni = g_n1[i];
#pragma unroll
        for (int c = 0; c < 4; c++) {
            const int j = j0 + tx * 4 + c;
            const float den = fmaxf(ni * g_n2[j], 1e-8f);
            g_sim[i * B + j] = acc[r][c] / den;
        }
    }
}

// ---------------- kernel 3: row/col maxes ----------------
// grid (B, 2), block 256. which==0: rowmax[j] = max over i (col read);
// which==1: colmax[i] = max over j (row read).
__global__ void max_kernel() {
    const int idx = blockIdx.x;
    const int which = blockIdx.y;
    const int tid = threadIdx.x;
    __shared__ float sm[256];
    float m = -INFINITY;
    if (which == 0) {
        for (int i = tid; i < B; i += 256)
            if (i != idx) m = fmaxf(m, g_sim[i * B + idx] * TINV);
    } else {
        for (int j = tid; j < B; j += 256)
            if (j != idx) m = fmaxf(m, g_sim[idx * B + j] * TINV);
    }
    sm[tid] = m;
    __syncthreads();
    for (int s = 128; s; s >>= 1) {
        if (tid < s) sm[tid] = fmaxf(sm[tid], sm[tid + s]);
        __syncthreads();
    }
    if (tid == 0) {
        const float pos = g_sim[idx * B + idx] * TINV;
        const float mm = fmaxf(pos, sm[0]);
        if (which == 0) g_rowmax[idx] = mm; else g_colmax[idx] = mm;
    }
}

// ---------------- kernel 4: denominators ----------------
// Reference semantics (note the asymmetry!):
//   row_den[i] = sum_{j!=i} exp(sim[i][j]/T - rowmax[j]) + exp(pos[i]-rowmax[i])
//                (rowmax[j] VARIES inside the sum)
//   col_den[j] = sum_{i!=j} exp(sim[i][j]/T - colmax[j]) + exp(pos[j]-colmax[j])
//                (colmax[j] is FIXED inside the sum)
__global__ void den_kernel() {
    const int idx = blockIdx.x;
    const int which = blockIdx.y;
    const int tid = threadIdx.x;
    __shared__ float sm[256];
    float s = 0.f;
    if (which == 0) {
        for (int j = tid; j < B; j += 256)
            if (j != idx) s += expf(g_sim[idx * B + j] * TINV - g_rowmax[j]);
    } else {
        const float cm = g_colmax[idx];
        for (int i = tid; i < B; i += 256)
            if (i != idx) s += expf(g_sim[i * B + idx] * TINV - cm);
    }
    sm[tid] = s;
    __syncthreads();
    for (int st = 128; st; st >>= 1) {
        if (tid < st) sm[tid] += sm[tid + st];
        __syncthreads();
    }
    if (tid == 0) {
        const float pos = g_sim[idx * B + idx] * TINV;
        if (which == 0) g_rowden[idx] = sm[0] + expf(pos - g_rowmax[idx]);
        else            g_colden[idx] = sm[0] + expf(pos - g_colmax[idx]);
    }
}

// ---------------- kernel 5: final loss ----------------
__global__ void loss_kernel(float* __restrict__ out) {
    const int tid = threadIdx.x;  // 512 threads
    __shared__ float sm[B];
    const float pos = g_sim[tid * B + tid] * TINV;
    const float rlog = logf(expf(pos - g_rowmax[tid]) / g_rowden[tid] + 1e-20f);
    const float clog = logf(expf(pos - g_colmax[tid]) / g_colden[tid] + 1e-20f);
    sm[tid] = -rlog - clog;
    __syncthreads();
    for (int s = 256; s; s >>= 1) {
        if (tid < s) sm[tid] += sm[tid + s];
        __syncthreads();
    }
    if (tid == 0) out[0] = sm[0] / (2.0f * (float)B);
}

extern "C" void kernel_launch(void* const* d_in, const int* in_sizes, int n_in,
                              void* d_out, int out_size) {
    const float* f1 = (const float*)d_in[0];
    const float* f2 = (const float*)d_in[1];
    const float* bb1 = (const float*)d_in[2];
    const float* bb2 = (const float*)d_in[3];
    float* out = (float*)d_out;

    desc_kernel<<<dim3(B, 2), 256>>>(f1, f2, bb1, bb2);
    sim_kernel<<<dim3(B / 64, B / 64), 256>>>();
    max_kernel<<<dim3(B, 2), 256>>>();
    den_kernel<<<dim3(B, 2), 256>>>();
    loss_kernel<<<1, B>>>(out);
}